// round 12
// baseline (speedup 1.0000x reference)
#include <cuda_runtime.h>
#include <cuda_fp16.h>
#include <cstdint>

#define BATCH 4
#define SEQ   4096
#define NEMB  1024
#define HD    128
#define Q_SCALE (0.03125f * 1.44269504088896340736f)   // 1/sqrt(1024) * log2(e)

// Scratch (device globals: allocation-free per harness rules)
__device__ __half g_qh [BATCH * SEQ * HD];    // q, pre-scaled, fp16
__device__ __half g_kh [BATCH * SEQ * HD];    // k, fp16
__device__ __half g_vth[BATCH * HD * SEQ];    // v transposed [b][h][t], fp16
__device__ __half g_xh [BATCH * SEQ * NEMB];  // x rounded to fp16
__device__ __half g_wth[3 * HD * NEMB];       // W^T hi fp16 [which][n][k]
__device__ __half g_wtl[3 * HD * NEMB];       // W^T lo fp16

__device__ __forceinline__ float ex2(float x) {
    float r; asm("ex2.approx.f32 %0, %1;" : "=f"(r) : "f"(x)); return r;
}
__device__ __forceinline__ uint32_t sptr(const void* p) {
    return (uint32_t)__cvta_generic_to_shared(p);
}
__device__ __forceinline__ void mma16(float* d, const uint32_t* a, uint32_t b0, uint32_t b1) {
    asm volatile(
        "mma.sync.aligned.m16n8k16.row.col.f32.f16.f16.f32 "
        "{%0,%1,%2,%3}, {%4,%5,%6,%7}, {%8,%9}, {%0,%1,%2,%3};"
        : "+f"(d[0]), "+f"(d[1]), "+f"(d[2]), "+f"(d[3])
        : "r"(a[0]), "r"(a[1]), "r"(a[2]), "r"(a[3]), "r"(b0), "r"(b1));
}
__device__ __forceinline__ void ldsm4(uint32_t* r, uint32_t a) {
    asm volatile("ldmatrix.sync.aligned.m8n8.x4.shared.b16 {%0,%1,%2,%3}, [%4];"
                 : "=r"(r[0]), "=r"(r[1]), "=r"(r[2]), "=r"(r[3]) : "r"(a));
}
__device__ __forceinline__ void cpa16(uint32_t dst, const void* src) {
    asm volatile("cp.async.cg.shared.global [%0], [%1], 16;" :: "r"(dst), "l"(src));
}
#define CP_COMMIT() asm volatile("cp.async.commit_group;" ::: "memory")
#define CP_WAIT1()  asm volatile("cp.async.wait_group 1;" ::: "memory")
#define CP_WAIT0()  asm volatile("cp.async.wait_group 0;" ::: "memory")
#define PAIR_BAR(id) asm volatile("bar.sync %0, 64;" :: "r"(id) : "memory")

// ---------------------------------------------------------------------------
// prep kernels
// ---------------------------------------------------------------------------
__global__ void prep_w(const float* __restrict__ Wq,
                       const float* __restrict__ Wk,
                       const float* __restrict__ Wv)
{
    int idx = blockIdx.x * 256 + threadIdx.x;      // 3*128*1024
    int which = idx >> 17;
    int r = idx & 131071;
    int n = r >> 10, k = r & 1023;
    const float* W = (which == 0) ? Wq : (which == 1) ? Wk : Wv;
    float v = W[(size_t)k * HD + n];
    __half h = __float2half_rn(v);
    g_wth[idx] = h;
    g_wtl[idx] = __float2half_rn(v - __half2float(h));
}

__global__ void prep_x(const float* __restrict__ x)
{
    size_t i = ((size_t)blockIdx.x * 256 + threadIdx.x) * 4;
    float4 v = *reinterpret_cast<const float4*>(x + i);
    *reinterpret_cast<__half2*>(g_xh + i)     = __floats2half2_rn(v.x, v.y);
    *reinterpret_cast<__half2*>(g_xh + i + 2) = __floats2half2_rn(v.z, v.w);
}

// ---------------------------------------------------------------------------
// QKV projection: fp16 mma, 2-term W split, 3-stage cp.async pipeline.
// (unchanged from round 10)
// ---------------------------------------------------------------------------
#define NSTG   3
#define PJ_LDH 40
#define PJ_SB  (128 * PJ_LDH * 2)
#define PJ_A(s)  ((s) * PJ_SB)
#define PJ_BH(s) ((NSTG + (s)) * PJ_SB)
#define PJ_BL(s) ((2 * NSTG + (s)) * PJ_SB)
#define PROJ_SMEM (3 * NSTG * PJ_SB)

__device__ __forceinline__ void proj_fill(char* smem, int s, int c, int m0, int tid,
                                          const __half* Wh, const __half* Wl)
{
    const int k0 = c * 32;
    const uint32_t sb = sptr(smem);
#pragma unroll
    for (int i = 0; i < 2; i++) {
        int q = tid + i * 256;
        int r = q >> 2, c16 = q & 3;
        uint32_t d = (uint32_t)(r * (PJ_LDH * 2) + c16 * 16);
        cpa16(sb + PJ_A(s)  + d, g_xh + (size_t)(m0 + r) * NEMB + k0 + c16 * 8);
        cpa16(sb + PJ_BH(s) + d, Wh + (size_t)r * NEMB + k0 + c16 * 8);
        cpa16(sb + PJ_BL(s) + d, Wl + (size_t)r * NEMB + k0 + c16 * 8);
    }
}

__global__ __launch_bounds__(256, 2) void proj_kernel()
{
    extern __shared__ char psm[];
    const uint32_t sb = sptr(psm);

    const int which = blockIdx.y;
    const __half* __restrict__ Wh = g_wth + which * (HD * NEMB);
    const __half* __restrict__ Wl = g_wtl + which * (HD * NEMB);

    const int m0   = blockIdx.x * 128;
    const int tid  = threadIdx.x;
    const int lane = tid & 31, wid = tid >> 5;
    const int wm = wid & 3, wn = wid >> 2;
    const int g = lane >> 2, t = lane & 3;
    const int arow = (lane & 7) + 8 * ((lane >> 3) & 1);
    const int asec = lane >> 4;
    const int brow = lane & 7;
    const int bsec = lane >> 3;

    float acc[2][8][4];
#pragma unroll
    for (int mt = 0; mt < 2; mt++)
#pragma unroll
        for (int nt = 0; nt < 8; nt++)
#pragma unroll
            for (int e = 0; e < 4; e++) acc[mt][nt][e] = 0.f;

    proj_fill(psm, 0, 0, m0, tid, Wh, Wl); CP_COMMIT();
    proj_fill(psm, 1, 1, m0, tid, Wh, Wl); CP_COMMIT();

#pragma unroll 1
    for (int c = 0; c < 32; c++) {
        if (c < 31) CP_WAIT1(); else CP_WAIT0();
        __syncthreads();
        if (c + 2 < 32) { proj_fill(psm, (c + 2) % 3, c + 2, m0, tid, Wh, Wl); CP_COMMIT(); }

        const int s = c % 3;
        uint32_t a[2][2][4];
#pragma unroll
        for (int mt = 0; mt < 2; mt++)
#pragma unroll
            for (int ks = 0; ks < 2; ks++)
                ldsm4(a[mt][ks], sb + PJ_A(s) +
                      ((wm * 32 + mt * 16 + arow) * PJ_LDH + ks * 16 + 8 * asec) * 2);
#pragma unroll
        for (int nt = 0; nt < 8; nt++) {
            int n0 = wn * 64 + nt * 8;
            uint32_t boff = (uint32_t)((n0 + brow) * PJ_LDH + 8 * bsec) * 2;
            uint32_t bh[4], bl[4];
            ldsm4(bh, sb + PJ_BH(s) + boff);
            ldsm4(bl, sb + PJ_BL(s) + boff);
#pragma unroll
            for (int mt = 0; mt < 2; mt++) {
                mma16(acc[mt][nt], a[mt][0], bh[0], bh[1]);
                mma16(acc[mt][nt], a[mt][1], bh[2], bh[3]);
                mma16(acc[mt][nt], a[mt][0], bl[0], bl[1]);
                mma16(acc[mt][nt], a[mt][1], bl[2], bl[3]);
            }
        }
    }

#pragma unroll
    for (int mt = 0; mt < 2; mt++)
#pragma unroll
        for (int nt = 0; nt < 8; nt++) {
            int row = m0 + wm * 32 + mt * 16 + g;
            int col = wn * 64 + nt * 8 + 2 * t;
            float v0 = acc[mt][nt][0], v1 = acc[mt][nt][1];
            float v2 = acc[mt][nt][2], v3 = acc[mt][nt][3];
            if (which == 0) { v0 *= Q_SCALE; v1 *= Q_SCALE; v2 *= Q_SCALE; v3 *= Q_SCALE; }
            if (which == 2) {
                int bb = row >> 12, tt = row & 4095;
                __half* vt = g_vth + (size_t)bb * (HD * SEQ) + tt;
                vt[(size_t)col * SEQ]           = __float2half_rn(v0);
                vt[(size_t)(col + 1) * SEQ]     = __float2half_rn(v1);
                vt[(size_t)col * SEQ + 8]       = __float2half_rn(v2);
                vt[(size_t)(col + 1) * SEQ + 8] = __float2half_rn(v3);
            } else {
                __half* outp = (which == 0) ? g_qh : g_kh;
                *reinterpret_cast<__half2*>(outp + (size_t)row * HD + col) =
                    __floats2half2_rn(v0, v1);
                *reinterpret_cast<__half2*>(outp + (size_t)(row + 8) * HD + col) =
                    __floats2half2_rn(v2, v3);
            }
        }
}

// ---------------------------------------------------------------------------
// Flash attention v2: 8 warps/CTA, pair-split columns.
// Pair (wlo, wlo+4) owns 16 Q rows. Side ws = w>>2:
//   S:  warp computes S[16][32]  (keys ws*32..+32)   -> s[4][4]
//   PV: warp computes O[16][64]  (head ws*64..+64)   -> o[8][4]
// Cross-pair softmax via named barriers + 1KB exchange smem.
// Smem 80KB: K[2][64][136]h, Vt[2][128][72]h, P[4][16][72]h, Ex[256]f.
// Target: <=128 regs -> 2 CTAs/SM -> 16 warps/SM.
// ---------------------------------------------------------------------------
#define K_LDH 136
#define V_LDH 72
#define P_LDH 72
#define AK_STRIDE (64 * K_LDH * 2)              // 17408
#define AV_STRIDE (128 * V_LDH * 2)             // 18432
#define A_KOFF 0
#define A_VOFF (2 * AK_STRIDE)                  // 34816
#define A_POFF (A_VOFF + 2 * AV_STRIDE)         // 71680
#define A_XOFF (A_POFF + 4 * 16 * P_LDH * 2)    // 80896
#define ATTN_SMEM (A_XOFF + 1024)               // 81920

__device__ __forceinline__ void attn_issue(char* smem, int buf, int jb, int tid,
                                           const __half* kg, const __half* vtg)
{
    const uint32_t sb = sptr(smem);
#pragma unroll
    for (int i = 0; i < 4; i++) {
        int q = tid + i * 256;
        int r = q >> 4, c16 = q & 15;           // K: 64 rows x 16 chunks
        cpa16(sb + A_KOFF + buf * AK_STRIDE + r * (K_LDH * 2) + c16 * 16,
              kg + (size_t)(jb * 64 + r) * HD + c16 * 8);
        int h = q >> 3, d16 = q & 7;            // V: 128 rows x 8 chunks
        cpa16(sb + A_VOFF + buf * AV_STRIDE + h * (V_LDH * 2) + d16 * 16,
              vtg + (size_t)h * SEQ + jb * 64 + d16 * 8);
    }
}

__global__ __launch_bounds__(256, 2) void attn_kernel(float* __restrict__ out)
{
    extern __shared__ char smc[];
    const uint32_t sb = sptr(smc);

    const int b  = blockIdx.y;
    const int bx = blockIdx.x;
    const int ib = (bx & 1) ? (SEQ / 64 - 1 - (bx >> 1)) : (bx >> 1);
    const int q0 = ib * 64;
    const int tid = threadIdx.x;
    const int lane = tid & 31, w = tid >> 5;
    const int wlo = w & 3, ws = w >> 2;         // pair id, column side
    const int g = lane >> 2, t = lane & 3;
    const int arow = (lane & 7) + 8 * ((lane >> 3) & 1);
    const int asec = lane >> 4;
    const int brow = lane & 7;
    const int bsec = lane >> 3;

    const __half* __restrict__ kg  = g_kh  + (size_t)b * SEQ * HD;
    const __half* __restrict__ vtg = g_vth + (size_t)b * HD * SEQ;

    float* ExM  = reinterpret_cast<float*>(smc + A_XOFF)       + (wlo * 2 + ws) * 16;
    float* ExMp = reinterpret_cast<float*>(smc + A_XOFF)       + (wlo * 2 + (ws ^ 1)) * 16;
    float* ExL  = reinterpret_cast<float*>(smc + A_XOFF + 512) + (wlo * 2 + ws) * 16;
    float* ExLp = reinterpret_cast<float*>(smc + A_XOFF + 512) + (wlo * 2 + (ws ^ 1)) * 16;
    __half* Pb  = reinterpret_cast<__half*>(smc + A_POFF) + wlo * (16 * P_LDH);

    // ---- stage Q (64 rows) into K buf 0, extract fp16 A-frags ----
    const __half* __restrict__ qg = g_qh + ((size_t)b * SEQ + q0) * HD;
#pragma unroll
    for (int i = 0; i < 4; i++) {
        int q = tid + i * 256;
        int r = q >> 4, c16 = q & 15;
        *reinterpret_cast<uint4*>(smc + A_KOFF + r * (K_LDH * 2) + c16 * 16) =
            *reinterpret_cast<const uint4*>(qg + (size_t)r * HD + c16 * 8);
    }
    __syncthreads();
    uint32_t qa[8][4];
    {
        uint32_t qb = sb + A_KOFF + ((16 * wlo + arow) * K_LDH + 8 * asec) * 2;
#pragma unroll
        for (int ks = 0; ks < 8; ks++) ldsm4(qa[ks], qb + ks * 32);
    }
    __syncthreads();
    attn_issue(smc, 0, 0, tid, kg, vtg); CP_COMMIT();

    float o[8][4];
#pragma unroll
    for (int nt = 0; nt < 8; nt++)
#pragma unroll
        for (int e = 0; e < 4; e++) o[nt][e] = 0.f;
    float m_lo = -1e30f, m_hi = -1e30f, l_lo = 0.f, l_hi = 0.f;

#pragma unroll 1
    for (int jb = 0; jb <= ib; jb++) {
        const int buf = jb & 1;
        if (jb < ib) {
            attn_issue(smc, buf ^ 1, jb + 1, tid, kg, vtg); CP_COMMIT(); CP_WAIT1();
        } else {
            CP_WAIT0();
        }
        __syncthreads();

        // ---- S half: 4 n-tiles (keys ws*32 + nt*8), k = 128 head dims ----
        float s[4][4];
#pragma unroll
        for (int nt = 0; nt < 4; nt++)
#pragma unroll
            for (int e = 0; e < 4; e++) s[nt][e] = 0.f;
#pragma unroll
        for (int nt = 0; nt < 4; nt++) {
            uint32_t ka = sb + A_KOFF + buf * AK_STRIDE +
                          ((ws * 32 + nt * 8 + brow) * K_LDH + 8 * bsec) * 2;
#pragma unroll
            for (int kc = 0; kc < 4; kc++) {
                uint32_t kb[4];
                ldsm4(kb, ka + kc * 64);
                mma16(s[nt], qa[2 * kc],     kb[0], kb[1]);
                mma16(s[nt], qa[2 * kc + 1], kb[2], kb[3]);
            }
        }

        // ---- causal mask (diagonal block) ----
        if (jb == ib) {
            int r_lo = 16 * wlo + g, r_hi = r_lo + 8;
#pragma unroll
            for (int nt = 0; nt < 4; nt++) {
                int cc = ws * 32 + nt * 8 + 2 * t;
                if (cc     > r_lo) s[nt][0] = -1e30f;
                if (cc + 1 > r_lo) s[nt][1] = -1e30f;
                if (cc     > r_hi) s[nt][2] = -1e30f;
                if (cc + 1 > r_hi) s[nt][3] = -1e30f;
            }
        }

        // ---- partial row max (own 32 cols), quad reduce ----
        float mx_lo = -1e30f, mx_hi = -1e30f;
#pragma unroll
        for (int nt = 0; nt < 4; nt++) {
            mx_lo = fmaxf(mx_lo, fmaxf(s[nt][0], s[nt][1]));
            mx_hi = fmaxf(mx_hi, fmaxf(s[nt][2], s[nt][3]));
        }
#pragma unroll
        for (int d = 1; d <= 2; d <<= 1) {
            mx_lo = fmaxf(mx_lo, __shfl_xor_sync(0xffffffffu, mx_lo, d));
            mx_hi = fmaxf(mx_hi, __shfl_xor_sync(0xffffffffu, mx_hi, d));
        }
        if (t == 0) { ExM[g] = mx_lo; ExM[g + 8] = mx_hi; }
        PAIR_BAR(1 + wlo);
        mx_lo = fmaxf(mx_lo, ExMp[g]);
        mx_hi = fmaxf(mx_hi, ExMp[g + 8]);

        float mn_lo = fmaxf(m_lo, mx_lo), mn_hi = fmaxf(m_hi, mx_hi);
        float al_lo = ex2(m_lo - mn_lo),  al_hi = ex2(m_hi - mn_hi);
        m_lo = mn_lo; m_hi = mn_hi;

        // ---- p = exp2(s - m); partial sums; write P half + partial l ----
        float ls_lo = 0.f, ls_hi = 0.f;
#pragma unroll
        for (int nt = 0; nt < 4; nt++) {
            s[nt][0] = ex2(s[nt][0] - mn_lo);
            s[nt][1] = ex2(s[nt][1] - mn_lo);
            s[nt][2] = ex2(s[nt][2] - mn_hi);
            s[nt][3] = ex2(s[nt][3] - mn_hi);
            ls_lo += s[nt][0] + s[nt][1];
            ls_hi += s[nt][2] + s[nt][3];
        }
#pragma unroll
        for (int d = 1; d <= 2; d <<= 1) {
            ls_lo += __shfl_xor_sync(0xffffffffu, ls_lo, d);
            ls_hi += __shfl_xor_sync(0xffffffffu, ls_hi, d);
        }
#pragma unroll
        for (int nt = 0; nt < 4; nt++) {
            int cc = ws * 32 + nt * 8 + 2 * t;
            *reinterpret_cast<__half2*>(Pb + g * P_LDH + cc) =
                __floats2half2_rn(s[nt][0], s[nt][1]);
            *reinterpret_cast<__half2*>(Pb + (g + 8) * P_LDH + cc) =
                __floats2half2_rn(s[nt][2], s[nt][3]);
        }
        if (t == 0) { ExL[g] = ls_lo; ExL[g + 8] = ls_hi; }

        // ---- rescale O while waiting ----
#pragma unroll
        for (int nt = 0; nt < 8; nt++) {
            o[nt][0] *= al_lo; o[nt][1] *= al_lo;
            o[nt][2] *= al_hi; o[nt][3] *= al_hi;
        }
        PAIR_BAR(1 + wlo);
        l_lo = l_lo * al_lo + ls_lo + ExLp[g];
        l_hi = l_hi * al_hi + ls_hi + ExLp[g + 8];

        // ---- PV: full P[16][64] x V half (head cols ws*64..+64) ----
        uint32_t pa[4][4];
        {
            uint32_t pu = sptr(Pb) + (arow * P_LDH + 8 * asec) * 2;
#pragma unroll
            for (int ks = 0; ks < 4; ks++) ldsm4(pa[ks], pu + ks * 32);
        }
#pragma unroll
        for (int nt = 0; nt < 8; nt++) {
            uint32_t va = sb + A_VOFF + buf * AV_STRIDE +
                          ((ws * 64 + nt * 8 + brow) * V_LDH + 8 * bsec) * 2;
#pragma unroll
            for (int kc = 0; kc < 2; kc++) {
                uint32_t vb[4];
                ldsm4(vb, va + kc * 64);
                mma16(o[nt], pa[2 * kc],     vb[0], vb[1]);
                mma16(o[nt], pa[2 * kc + 1], vb[2], vb[3]);
            }
        }
        __syncthreads();
    }

    // ---- epilogue: warp writes its 64 head cols ----
    float inv_lo = 1.f / l_lo, inv_hi = 1.f / l_hi;
    float* __restrict__ og = out + ((size_t)b * SEQ + q0) * HD;
    int r_lo = 16 * wlo + g;
#pragma unroll
    for (int nt = 0; nt < 8; nt++) {
        int col = ws * 64 + nt * 8 + 2 * t;
        *reinterpret_cast<float2*>(og + (size_t)r_lo * HD + col) =
            make_float2(o[nt][0] * inv_lo, o[nt][1] * inv_lo);
        *reinterpret_cast<float2*>(og + (size_t)(r_lo + 8) * HD + col) =
            make_float2(o[nt][2] * inv_hi, o[nt][3] * inv_hi);
    }
}

// ---------------------------------------------------------------------------
extern "C" void kernel_launch(void* const* d_in, const int* in_sizes, int n_in,
                              void* d_out, int out_size)
{
    const float* x  = (const float*)d_in[0];
    const float* Wq = (const float*)d_in[1];
    const float* Wk = (const float*)d_in[2];
    const float* Wv = (const float*)d_in[3];
    float* out = (float*)d_out;

    cudaFuncSetAttribute(proj_kernel, cudaFuncAttributeMaxDynamicSharedMemorySize,
                         PROJ_SMEM);
    cudaFuncSetAttribute(attn_kernel, cudaFuncAttributeMaxDynamicSharedMemorySize,
                         ATTN_SMEM);

    prep_w<<<(3 * HD * NEMB) / 256, 256>>>(Wq, Wk, Wv);
    prep_x<<<(BATCH * SEQ * NEMB) / 1024, 256>>>(x);

    dim3 pg(BATCH * SEQ / 128, 3);
    proj_kernel<<<pg, 256, PROJ_SMEM>>>();

    dim3 ag(SEQ / 64, BATCH);
    attn_kernel<<<ag, 256, ATTN_SMEM>>>(out);
}